// round 2
// baseline (speedup 1.0000x reference)
#include <cuda_runtime.h>
#include <cuda_fp16.h>
#include <math.h>

#define NB 4
#define DD 16
#define HH 512
#define WW 512
#define PLANE (HH*WW)
#define VOL (DD*PLANE)
#define TOT (NB*VOL)
#define C1F 0.0001f
#define C2F 0.0009f

typedef unsigned long long ull;

// 5 blurred fields (p, g, p^2, g^2, p*g), fp16, each [N*D, H, W]
__device__ __half g_blur[5][TOT];
// [0..3] per-n sum (p-g)^2 ; [4..7] per-n sum ssim_map
__device__ double g_acc[8];

struct GaussW { float w[11]; };

__device__ __forceinline__ ull fma2(ull a, ull b, ull c) {
    ull d; asm("fma.rn.f32x2 %0,%1,%2,%3;" : "=l"(d) : "l"(a), "l"(b), "l"(c)); return d;
}
__device__ __forceinline__ ull pack2f(float lo, float hi) {
    ull r; asm("mov.b64 %0,{%1,%2};" : "=l"(r) : "f"(lo), "f"(hi)); return r;
}
__device__ __forceinline__ void unpack2(ull v, float& a, float& b) {
    asm("mov.b64 {%0,%1},%2;" : "=f"(a), "=f"(b) : "l"(v));
}

__global__ void zero_acc_kernel() {
    int i = threadIdx.x;
    if (i < 8) g_acc[i] = 0.0;
}

struct SmemLoad {
    float2 s01[42][45];   // (p, g)
    float2 s23[42][45];   // (p^2, g^2)
    float  s4[42][45];    // p*g
};
struct SmemTmp {
    float2 t01[42][32];
    float2 t23[42][32];
    float  t4[42][32];
};

// Fused field-gen + W-blur + H-blur for one (n,d) slice tile; PSNR partials fused.
__global__ __launch_bounds__(256, 2) void blur2d_kernel(
    const float* __restrict__ pred, const float* __restrict__ gt, GaussW gw)
{
    __shared__ union { SmemLoad a; SmemTmp b; } sm;
    __shared__ float red[256];

    int z = blockIdx.z;
    int n = z >> 4;
    const float* pz = pred + (size_t)z * PLANE;
    const float* gz = gt   + (size_t)z * PLANE;
    int h0 = blockIdx.y * 32 - 5;
    int w0 = blockIdx.x * 32 - 5;
    int tid = threadIdx.x;

    // Packed weights in registers
    ull   W2[11];
    float wf[11];
    #pragma unroll
    for (int k = 0; k < 11; k++) { wf[k] = gw.w[k]; W2[k] = pack2f(wf[k], wf[k]); }

    // ---- Load 42x42 tile (clamped) + per-element field precompute ----
    for (int i = tid; i < 42*42; i += 256) {
        int r = i / 42, c = i - r*42;
        int hh = min(max(h0 + r, 0), HH-1);
        int ww = min(max(w0 + c, 0), WW-1);
        float p = pz[hh*WW + ww];
        float g = gz[hh*WW + ww];
        sm.a.s01[r][c] = make_float2(p, g);
        sm.a.s23[r][c] = make_float2(p*p, g*g);
        sm.a.s4[r][c]  = p * g;
    }
    __syncthreads();

    // ---- PSNR partial over interior 32x32 ----
    float psum = 0.f;
    for (int i = tid; i < 1024; i += 256) {
        int r = 5 + (i >> 5), c = 5 + (i & 31);
        float2 v = sm.a.s01[r][c];
        float d = v.x - v.y;
        psum = fmaf(d, d, psum);
    }

    // ---- W-blur: 42 rows x 4 chunks of 8 outputs; results held in registers ----
    ull acc01[8], acc23[8]; float acc4[8];
    #pragma unroll
    for (int o = 0; o < 8; o++) { acc01[o] = 0ull; acc23[o] = 0ull; acc4[o] = 0.f; }
    bool act = (tid < 168);
    int r = 0, ch = 0;
    if (act) {
        r = tid >> 2; ch = (tid & 3) * 8;
        #pragma unroll
        for (int k = 0; k < 18; k++) {
            ull v01 = *(const ull*)&sm.a.s01[r][ch + k];
            ull v23 = *(const ull*)&sm.a.s23[r][ch + k];
            float v4 = sm.a.s4[r][ch + k];
            #pragma unroll
            for (int o = 0; o < 8; o++) {
                int t = k - o;
                if (t >= 0 && t <= 10) {
                    acc01[o] = fma2(W2[t], v01, acc01[o]);
                    acc23[o] = fma2(W2[t], v23, acc23[o]);
                    acc4[o]  = fmaf(wf[t], v4, acc4[o]);
                }
            }
        }
    }
    __syncthreads();   // all reads of sm.a done

    if (act) {
        #pragma unroll
        for (int o = 0; o < 8; o++) {
            *(ull*)&sm.b.t01[r][ch + o] = acc01[o];
            *(ull*)&sm.b.t23[r][ch + o] = acc23[o];
            sm.b.t4[r][ch + o] = acc4[o];
        }
    }
    __syncthreads();

    // ---- H-blur + fp16 store ----
    int hb = blockIdx.y * 32, wb = blockIdx.x * 32;

    // Pass A: packed field pairs {p,g} and {p2,g2}: 2 grp x 4 hch x 32 c = 256
    {
        int grp = tid >> 7;
        int rem = tid & 127;
        int hch = rem >> 5;
        int c   = rem & 31;
        const float2 (*tp)[32] = (grp == 0) ? sm.b.t01 : sm.b.t23;
        ull acc[8];
        #pragma unroll
        for (int o = 0; o < 8; o++) acc[o] = 0ull;
        #pragma unroll
        for (int k = 0; k < 18; k++) {
            ull v = *(const ull*)&tp[hch*8 + k][c];
            #pragma unroll
            for (int o = 0; o < 8; o++) {
                int t = k - o;
                if (t >= 0 && t <= 10) acc[o] = fma2(W2[t], v, acc[o]);
            }
        }
        __half* o0 = &g_blur[grp*2    ][(size_t)z * PLANE];
        __half* o1 = &g_blur[grp*2 + 1][(size_t)z * PLANE];
        #pragma unroll
        for (int o = 0; o < 8; o++) {
            float x, y; unpack2(acc[o], x, y);
            int row = hb + hch*8 + o;
            o0[row*WW + wb + c] = __float2half_rn(x);
            o1[row*WW + wb + c] = __float2half_rn(y);
        }
    }
    // Pass B: scalar field p*g: 4 hch x 32 c = 128 (half the threads)
    if (tid < 128) {
        int hch = tid >> 5;
        int c   = tid & 31;
        float acc[8];
        #pragma unroll
        for (int o = 0; o < 8; o++) acc[o] = 0.f;
        #pragma unroll
        for (int k = 0; k < 18; k++) {
            float v = sm.b.t4[hch*8 + k][c];
            #pragma unroll
            for (int o = 0; o < 8; o++) {
                int t = k - o;
                if (t >= 0 && t <= 10) acc[o] = fmaf(wf[t], v, acc[o]);
            }
        }
        __half* o4 = &g_blur[4][(size_t)z * PLANE];
        #pragma unroll
        for (int o = 0; o < 8; o++) {
            int row = hb + hch*8 + o;
            o4[row*WW + wb + c] = __float2half_rn(acc[o]);
        }
    }

    // ---- PSNR block reduce ----
    red[tid] = psum;
    __syncthreads();
    #pragma unroll
    for (int s = 128; s > 0; s >>= 1) {
        if (tid < s) red[tid] += red[tid + s];
        __syncthreads();
    }
    if (tid == 0) atomicAdd(&g_acc[n], (double)red[0]);
}

// D-blur in registers (D=16) + SSIM pointwise + reduction; packed f32x2.
__global__ __launch_bounds__(256, 2) void ssim_d_kernel(GaussW gw) {
    int tid = threadIdx.x;
    int idx = blockIdx.x * 256 + tid;
    int n   = blockIdx.y;
    size_t base = (size_t)n * VOL + idx;

    ull   W2[11];
    float wf[11];
    #pragma unroll
    for (int k = 0; k < 11; k++) { wf[k] = gw.w[k]; W2[k] = pack2f(wf[k], wf[k]); }

    ull in01[16], in23[16]; float in4[16];
    #pragma unroll
    for (int d = 0; d < 16; d++) {
        size_t off = base + (size_t)d * PLANE;
        float f0 = __half2float(g_blur[0][off]);
        float f1 = __half2float(g_blur[1][off]);
        float f2 = __half2float(g_blur[2][off]);
        float f3 = __half2float(g_blur[3][off]);
        float f4 = __half2float(g_blur[4][off]);
        in01[d] = pack2f(f0, f1);
        in23[d] = pack2f(f2, f3);
        in4[d]  = f4;
    }

    float ssum = 0.f;
    #pragma unroll
    for (int d = 0; d < 16; d++) {
        ull a01 = 0ull, a23 = 0ull; float a4 = 0.f;
        #pragma unroll
        for (int k = 0; k < 11; k++) {
            int dd = d - 5 + k;
            dd = dd < 0 ? 0 : (dd > 15 ? 15 : dd);
            a01 = fma2(W2[k], in01[dd], a01);
            a23 = fma2(W2[k], in23[dd], a23);
            a4  = fmaf(wf[k], in4[dd], a4);
        }
        float mu1, mu2, b2, b3;
        unpack2(a01, mu1, mu2);
        unpack2(a23, b2, b3);
        float mu1s = mu1*mu1, mu2s = mu2*mu2, mu12 = mu1*mu2;
        float s1 = b2 - mu1s, s2 = b3 - mu2s, s12 = a4 - mu12;
        float v1 = 2.f*s12 + C2F;
        float v2 = s1 + s2 + C2F;
        float num = (2.f*mu12 + C1F) * v1;
        float den = (mu1s + mu2s + C1F) * v2;
        ssum += __fdividef(num, den);
    }

    __shared__ float red[256];
    red[tid] = ssum;
    __syncthreads();
    #pragma unroll
    for (int s = 128; s > 0; s >>= 1) {
        if (tid < s) red[tid] += red[tid + s];
        __syncthreads();
    }
    if (tid == 0) atomicAdd(&g_acc[4 + n], (double)red[0]);
}

__global__ void final_kernel(float* out, int out_size) {
    if (threadIdx.x == 0 && blockIdx.x == 0) {
        double psnr = 0.0, ssim = 0.0;
        for (int n = 0; n < NB; n++) {
            double mse = g_acc[n] / (double)VOL;
            psnr += 10.0 * log10(1.0 / mse);
            ssim += g_acc[4 + n] / (double)VOL;
        }
        if (out_size > 0) out[0] = (float)psnr;
        if (out_size > 1) out[1] = (float)ssim;
        if (out_size > 2) out[2] = (float)NB;
        for (int i = 3; i < out_size; i++) out[i] = 0.f;
    }
}

extern "C" void kernel_launch(void* const* d_in, const int* in_sizes, int n_in,
                              void* d_out, int out_size) {
    const float* pred = (const float*)d_in[0];
    const float* gt   = (const float*)d_in[1];

    GaussW gw;
    double wd[11], s = 0.0;
    for (int i = 0; i < 11; i++) { double x = (double)(i - 5); wd[i] = exp(-x*x/4.5); s += wd[i]; }
    for (int i = 0; i < 11; i++) gw.w[i] = (float)(wd[i]/s);

    zero_acc_kernel<<<1, 32>>>();

    dim3 g1(WW/32, HH/32, NB*DD);
    blur2d_kernel<<<g1, 256>>>(pred, gt, gw);

    dim3 g2(PLANE/256, NB);
    ssim_d_kernel<<<g2, 256>>>(gw);

    final_kernel<<<1, 32>>>((float*)d_out, out_size);
}

// round 3
// speedup vs baseline: 1.3262x; 1.3262x over previous
#include <cuda_runtime.h>
#include <cuda_fp16.h>
#include <math.h>

#define NB 4
#define DD 16
#define HH 512
#define WW 512
#define PLANE (HH*WW)
#define VOL (DD*PLANE)
#define TOT (NB*VOL)
#define C1F 0.0001f
#define C2F 0.0009f

typedef unsigned long long ull;

// 5 blurred fields (p, g, p^2, g^2, p*g), fp16, each [N*D, H, W]
__device__ __half g_blur[5][TOT];
// [0..3] per-n sum (p-g)^2 ; [4..7] per-n sum ssim_map
__device__ double g_acc[8];

struct GaussW { float w[11]; };

__device__ __forceinline__ ull fma2(ull a, ull b, ull c) {
    ull d; asm("fma.rn.f32x2 %0,%1,%2,%3;" : "=l"(d) : "l"(a), "l"(b), "l"(c)); return d;
}
__device__ __forceinline__ ull pack2f(float lo, float hi) {
    ull r; asm("mov.b64 %0,{%1,%2};" : "=l"(r) : "f"(lo), "f"(hi)); return r;
}
__device__ __forceinline__ void unpack2(ull v, float& a, float& b) {
    asm("mov.b64 {%0,%1},%2;" : "=f"(a), "=f"(b) : "l"(v));
}

__global__ void zero_acc_kernel() {
    int i = threadIdx.x;
    if (i < 8) g_acc[i] = 0.0;
}

// Fused field-gen + W-blur + H-blur per (n,d) slice tile; PSNR partials fused.
// Three field-group passes, each with a small register window (no spills).
__global__ __launch_bounds__(256) void blur2d_kernel(
    const float* __restrict__ pred, const float* __restrict__ gt, GaussW gw)
{
    __shared__ float2 s01[42][44];   // (p, g)
    __shared__ float2 s23[42][44];   // (p^2, g^2)
    __shared__ float  s4[42][44];    // p*g
    __shared__ union {
        float2 t2[42][32];
        float  t1[42][32];
        float  red[256];
    } u;

    int z = blockIdx.z;
    int n = z >> 4;
    const float* pz = pred + (size_t)z * PLANE;
    const float* gz = gt   + (size_t)z * PLANE;
    int h0 = blockIdx.y * 32 - 5;
    int w0 = blockIdx.x * 32 - 5;
    int hb = blockIdx.y * 32, wb = blockIdx.x * 32;
    int tid = threadIdx.x;

    ull   W2[11];
    float wf[11];
    #pragma unroll
    for (int k = 0; k < 11; k++) { wf[k] = gw.w[k]; W2[k] = pack2f(wf[k], wf[k]); }

    // ---- Load 42x42 tile (clamped = replicate pad) + field precompute ----
    for (int i = tid; i < 42*42; i += 256) {
        int r = i / 42, c = i - r*42;
        int hh = min(max(h0 + r, 0), HH-1);
        int ww = min(max(w0 + c, 0), WW-1);
        float p = pz[hh*WW + ww];
        float g = gz[hh*WW + ww];
        s01[r][c] = make_float2(p, g);
        s23[r][c] = make_float2(p*p, g*g);
        s4[r][c]  = p * g;
    }
    __syncthreads();

    // ---- PSNR partial over interior 32x32 (reads s01 only; no write conflicts) ----
    float psum = 0.f;
    for (int i = tid; i < 1024; i += 256) {
        int r = 5 + (i >> 5), c = 5 + (i & 31);
        float2 v = s01[r][c];
        float d = v.x - v.y;
        psum = fmaf(d, d, psum);
    }

    // ======== Field-group pass: {p, g} (packed) ========
    for (int it = tid; it < 168; it += 256) {
        int r = it >> 2, ch = (it & 3) * 8;
        ull v[18];
        #pragma unroll
        for (int k = 0; k < 18; k++) v[k] = *(const ull*)&s01[r][ch + k];
        #pragma unroll
        for (int o = 0; o < 8; o++) {
            ull a = 0ull;
            #pragma unroll
            for (int k = 0; k < 11; k++) a = fma2(W2[k], v[o + k], a);
            *(ull*)&u.t2[r][ch + o] = a;
        }
    }
    __syncthreads();
    for (int it = tid; it < 128; it += 256) {
        int hch = it >> 5, c = it & 31;
        ull v[18];
        #pragma unroll
        for (int k = 0; k < 18; k++) v[k] = *(const ull*)&u.t2[hch*8 + k][c];
        __half* o0 = &g_blur[0][(size_t)z * PLANE];
        __half* o1 = &g_blur[1][(size_t)z * PLANE];
        #pragma unroll
        for (int o = 0; o < 8; o++) {
            ull a = 0ull;
            #pragma unroll
            for (int k = 0; k < 11; k++) a = fma2(W2[k], v[o + k], a);
            float x, y; unpack2(a, x, y);
            int row = hb + hch*8 + o;
            o0[row*WW + wb + c] = __float2half_rn(x);
            o1[row*WW + wb + c] = __float2half_rn(y);
        }
    }
    __syncthreads();

    // ======== Field-group pass: {p^2, g^2} (packed) ========
    for (int it = tid; it < 168; it += 256) {
        int r = it >> 2, ch = (it & 3) * 8;
        ull v[18];
        #pragma unroll
        for (int k = 0; k < 18; k++) v[k] = *(const ull*)&s23[r][ch + k];
        #pragma unroll
        for (int o = 0; o < 8; o++) {
            ull a = 0ull;
            #pragma unroll
            for (int k = 0; k < 11; k++) a = fma2(W2[k], v[o + k], a);
            *(ull*)&u.t2[r][ch + o] = a;
        }
    }
    __syncthreads();
    for (int it = tid; it < 128; it += 256) {
        int hch = it >> 5, c = it & 31;
        ull v[18];
        #pragma unroll
        for (int k = 0; k < 18; k++) v[k] = *(const ull*)&u.t2[hch*8 + k][c];
        __half* o2 = &g_blur[2][(size_t)z * PLANE];
        __half* o3 = &g_blur[3][(size_t)z * PLANE];
        #pragma unroll
        for (int o = 0; o < 8; o++) {
            ull a = 0ull;
            #pragma unroll
            for (int k = 0; k < 11; k++) a = fma2(W2[k], v[o + k], a);
            float x, y; unpack2(a, x, y);
            int row = hb + hch*8 + o;
            o2[row*WW + wb + c] = __float2half_rn(x);
            o3[row*WW + wb + c] = __float2half_rn(y);
        }
    }
    __syncthreads();

    // ======== Field-group pass: p*g (scalar) ========
    for (int it = tid; it < 168; it += 256) {
        int r = it >> 2, ch = (it & 3) * 8;
        float v[18];
        #pragma unroll
        for (int k = 0; k < 18; k++) v[k] = s4[r][ch + k];
        #pragma unroll
        for (int o = 0; o < 8; o++) {
            float a = 0.f;
            #pragma unroll
            for (int k = 0; k < 11; k++) a = fmaf(wf[k], v[o + k], a);
            u.t1[r][ch + o] = a;
        }
    }
    __syncthreads();
    for (int it = tid; it < 128; it += 256) {
        int hch = it >> 5, c = it & 31;
        float v[18];
        #pragma unroll
        for (int k = 0; k < 18; k++) v[k] = u.t1[hch*8 + k][c];
        __half* o4 = &g_blur[4][(size_t)z * PLANE];
        #pragma unroll
        for (int o = 0; o < 8; o++) {
            float a = 0.f;
            #pragma unroll
            for (int k = 0; k < 11; k++) a = fmaf(wf[k], v[o + k], a);
            int row = hb + hch*8 + o;
            o4[row*WW + wb + c] = __float2half_rn(a);
        }
    }
    __syncthreads();

    // ---- PSNR block reduce (tmp buffer is dead now) ----
    u.red[tid] = psum;
    __syncthreads();
    #pragma unroll
    for (int s = 128; s > 0; s >>= 1) {
        if (tid < s) u.red[tid] += u.red[tid + s];
        __syncthreads();
    }
    if (tid == 0) atomicAdd(&g_acc[n], (double)u.red[0]);
}

// D-blur in registers (D=16, clamped) + SSIM pointwise + reduction.
__global__ __launch_bounds__(256) void ssim_d_kernel(GaussW gw) {
    int tid = threadIdx.x;
    int idx = blockIdx.x * 256 + tid;
    int n   = blockIdx.y;
    size_t base = (size_t)n * VOL + idx;

    ull   W2[11];
    float wf[11];
    #pragma unroll
    for (int k = 0; k < 11; k++) { wf[k] = gw.w[k]; W2[k] = pack2f(wf[k], wf[k]); }

    ull in01[16], in23[16]; float in4[16];
    #pragma unroll
    for (int d = 0; d < 16; d++) {
        size_t off = base + (size_t)d * PLANE;
        in01[d] = pack2f(__half2float(g_blur[0][off]), __half2float(g_blur[1][off]));
        in23[d] = pack2f(__half2float(g_blur[2][off]), __half2float(g_blur[3][off]));
        in4[d]  = __half2float(g_blur[4][off]);
    }

    float ssum = 0.f;
    #pragma unroll
    for (int d = 0; d < 16; d++) {
        ull a01 = 0ull, a23 = 0ull; float a4 = 0.f;
        #pragma unroll
        for (int k = 0; k < 11; k++) {
            int dd = d - 5 + k;
            dd = dd < 0 ? 0 : (dd > 15 ? 15 : dd);   // compile-time after unroll
            a01 = fma2(W2[k], in01[dd], a01);
            a23 = fma2(W2[k], in23[dd], a23);
            a4  = fmaf(wf[k], in4[dd], a4);
        }
        float mu1, mu2, b2, b3;
        unpack2(a01, mu1, mu2);
        unpack2(a23, b2, b3);
        float mu1s = mu1*mu1, mu2s = mu2*mu2, mu12 = mu1*mu2;
        float s1 = b2 - mu1s, s2 = b3 - mu2s, s12 = a4 - mu12;
        float v1 = 2.f*s12 + C2F;
        float v2 = s1 + s2 + C2F;
        float num = (2.f*mu12 + C1F) * v1;
        float den = (mu1s + mu2s + C1F) * v2;
        ssum += __fdividef(num, den);
    }

    __shared__ float red[256];
    red[tid] = ssum;
    __syncthreads();
    #pragma unroll
    for (int s = 128; s > 0; s >>= 1) {
        if (tid < s) red[tid] += red[tid + s];
        __syncthreads();
    }
    if (tid == 0) atomicAdd(&g_acc[4 + n], (double)red[0]);
}

__global__ void final_kernel(float* out, int out_size) {
    if (threadIdx.x == 0 && blockIdx.x == 0) {
        double psnr = 0.0, ssim = 0.0;
        for (int n = 0; n < NB; n++) {
            double mse = g_acc[n] / (double)VOL;
            psnr += 10.0 * log10(1.0 / mse);
            ssim += g_acc[4 + n] / (double)VOL;
        }
        if (out_size > 0) out[0] = (float)psnr;
        if (out_size > 1) out[1] = (float)ssim;
        if (out_size > 2) out[2] = (float)NB;
        for (int i = 3; i < out_size; i++) out[i] = 0.f;
    }
}

extern "C" void kernel_launch(void* const* d_in, const int* in_sizes, int n_in,
                              void* d_out, int out_size) {
    const float* pred = (const float*)d_in[0];
    const float* gt   = (const float*)d_in[1];

    GaussW gw;
    double wd[11], s = 0.0;
    for (int i = 0; i < 11; i++) { double x = (double)(i - 5); wd[i] = exp(-x*x/4.5); s += wd[i]; }
    for (int i = 0; i < 11; i++) gw.w[i] = (float)(wd[i]/s);

    zero_acc_kernel<<<1, 32>>>();

    dim3 g1(WW/32, HH/32, NB*DD);
    blur2d_kernel<<<g1, 256>>>(pred, gt, gw);

    dim3 g2(PLANE/256, NB);
    ssim_d_kernel<<<g2, 256>>>(gw);

    final_kernel<<<1, 32>>>((float*)d_out, out_size);
}

// round 4
// speedup vs baseline: 1.3370x; 1.0081x over previous
#include <cuda_runtime.h>
#include <cuda_fp16.h>
#include <math.h>

#define NB 4
#define DD 16
#define HH 512
#define WW 512
#define PLANE (HH*WW)
#define VOL (DD*PLANE)
#define TOT (NB*VOL)
#define C1F 0.0001f
#define C2F 0.0009f

// Gaussian weights (sigma=1.5, wsize=11), precomputed in double, as LITERALS so
// ptxas emits FFMA-imm (rt_SMSP=1, 2x throughput of 3-reg FFMA).
#define GW0 0.00102838f
#define GW1 0.00759875f
#define GW2 0.03600077f
#define GW3 0.10936069f
#define GW4 0.21300554f
#define GW5 0.26601173f

// Blurred fields, fp16: (p,g) packed, (p^2,g^2) packed, p*g scalar. [N*D,H,W]
__device__ __half2 g01[TOT];
__device__ __half2 g23[TOT];
__device__ __half  g4v[TOT];
// [0..3] per-n sum (p-g)^2 ; [4..7] per-n sum ssim_map. Zero-init at load;
// final_kernel re-zeroes after reading so every replay starts from zero.
__device__ double g_acc[8];

__device__ __forceinline__ float blur11(const float* v) {
    float a;
    a = v[0]  * GW0;
    a = fmaf(v[1],  GW1, a);
    a = fmaf(v[2],  GW2, a);
    a = fmaf(v[3],  GW3, a);
    a = fmaf(v[4],  GW4, a);
    a = fmaf(v[5],  GW5, a);
    a = fmaf(v[6],  GW4, a);
    a = fmaf(v[7],  GW3, a);
    a = fmaf(v[8],  GW2, a);
    a = fmaf(v[9],  GW1, a);
    a = fmaf(v[10], GW0, a);
    return a;
}

// Fused field-gen + W-blur + H-blur per (n,d) slice tile; PSNR partials fused.
__global__ __launch_bounds__(256) void blur2d_kernel(
    const float* __restrict__ pred, const float* __restrict__ gt)
{
    __shared__ float2 s01[42][44];   // (p, g)
    __shared__ float2 s23[42][44];   // (p^2, g^2)
    __shared__ float  s4[42][44];    // p*g
    __shared__ union {
        float2 t2[42][32];
        float  t1[42][32];
        float  red[256];
    } u;

    int z = blockIdx.z;
    int n = z >> 4;
    const float* pz = pred + (size_t)z * PLANE;
    const float* gz = gt   + (size_t)z * PLANE;
    int h0 = blockIdx.y * 32 - 5;
    int w0 = blockIdx.x * 32 - 5;
    int hb = blockIdx.y * 32, wb = blockIdx.x * 32;
    int tid = threadIdx.x;

    // ---- Load 42x42 tile (clamped = replicate pad) + field precompute ----
    for (int i = tid; i < 42*42; i += 256) {
        int r = i / 42, c = i - r*42;
        int hh = min(max(h0 + r, 0), HH-1);
        int ww = min(max(w0 + c, 0), WW-1);
        float p = pz[hh*WW + ww];
        float g = gz[hh*WW + ww];
        s01[r][c] = make_float2(p, g);
        s23[r][c] = make_float2(p*p, g*g);
        s4[r][c]  = p * g;
    }
    __syncthreads();

    // ---- PSNR partial over interior 32x32 ----
    float psum = 0.f;
    #pragma unroll
    for (int i = 0; i < 4; i++) {
        int j = tid + i*256;
        int r = 5 + (j >> 5), c = 5 + (j & 31);
        float2 v = s01[r][c];
        float d = v.x - v.y;
        psum = fmaf(d, d, psum);
    }

    int rW = tid >> 2, chW = (tid & 3) * 8;   // W-pass coords (tid < 168)
    int hch = tid >> 5, cH = tid & 31;        // H-pass coords (tid < 128)

    // ======== Field-group pass: {p, g} ========
    if (tid < 168) {
        float vx[18], vy[18];
        #pragma unroll
        for (int k = 0; k < 18; k++) {
            float2 v = s01[rW][chW + k];
            vx[k] = v.x; vy[k] = v.y;
        }
        #pragma unroll
        for (int o = 0; o < 8; o++)
            u.t2[rW][chW + o] = make_float2(blur11(vx + o), blur11(vy + o));
    }
    __syncthreads();
    if (tid < 128) {
        float vx[18], vy[18];
        #pragma unroll
        for (int k = 0; k < 18; k++) {
            float2 v = u.t2[hch*8 + k][cH];
            vx[k] = v.x; vy[k] = v.y;
        }
        __half2* o01 = &g01[(size_t)z * PLANE];
        #pragma unroll
        for (int o = 0; o < 8; o++) {
            int row = hb + hch*8 + o;
            o01[row*WW + wb + cH] = __floats2half2_rn(blur11(vx + o), blur11(vy + o));
        }
    }
    __syncthreads();

    // ======== Field-group pass: {p^2, g^2} ========
    if (tid < 168) {
        float vx[18], vy[18];
        #pragma unroll
        for (int k = 0; k < 18; k++) {
            float2 v = s23[rW][chW + k];
            vx[k] = v.x; vy[k] = v.y;
        }
        #pragma unroll
        for (int o = 0; o < 8; o++)
            u.t2[rW][chW + o] = make_float2(blur11(vx + o), blur11(vy + o));
    }
    __syncthreads();
    if (tid < 128) {
        float vx[18], vy[18];
        #pragma unroll
        for (int k = 0; k < 18; k++) {
            float2 v = u.t2[hch*8 + k][cH];
            vx[k] = v.x; vy[k] = v.y;
        }
        __half2* o23 = &g23[(size_t)z * PLANE];
        #pragma unroll
        for (int o = 0; o < 8; o++) {
            int row = hb + hch*8 + o;
            o23[row*WW + wb + cH] = __floats2half2_rn(blur11(vx + o), blur11(vy + o));
        }
    }
    __syncthreads();

    // ======== Field-group pass: p*g ========
    if (tid < 168) {
        float v[18];
        #pragma unroll
        for (int k = 0; k < 18; k++) v[k] = s4[rW][chW + k];
        #pragma unroll
        for (int o = 0; o < 8; o++)
            u.t1[rW][chW + o] = blur11(v + o);
    }
    __syncthreads();
    if (tid < 128) {
        float v[18];
        #pragma unroll
        for (int k = 0; k < 18; k++) v[k] = u.t1[hch*8 + k][cH];
        __half* o4 = &g4v[(size_t)z * PLANE];
        #pragma unroll
        for (int o = 0; o < 8; o++) {
            int row = hb + hch*8 + o;
            o4[row*WW + wb + cH] = __float2half_rn(blur11(v + o));
        }
    }
    __syncthreads();

    // ---- PSNR block reduce ----
    u.red[tid] = psum;
    __syncthreads();
    #pragma unroll
    for (int s = 128; s > 0; s >>= 1) {
        if (tid < s) u.red[tid] += u.red[tid + s];
        __syncthreads();
    }
    if (tid == 0) atomicAdd(&g_acc[n], (double)u.red[0]);
}

// D-blur in registers (D=16, clamped) + SSIM pointwise + reduction.
__global__ __launch_bounds__(256) void ssim_d_kernel() {
    int tid = threadIdx.x;
    int idx = blockIdx.x * 256 + tid;
    int n   = blockIdx.y;
    size_t base = (size_t)n * VOL + idx;

    float i0[16], i1[16], i2[16], i3[16], i4[16];
    #pragma unroll
    for (int d = 0; d < 16; d++) {
        size_t off = base + (size_t)d * PLANE;
        float2 a = __half22float2(g01[off]);
        float2 b = __half22float2(g23[off]);
        i0[d] = a.x; i1[d] = a.y;
        i2[d] = b.x; i3[d] = b.y;
        i4[d] = __half2float(g4v[off]);
    }

    const float wq[11] = {GW0,GW1,GW2,GW3,GW4,GW5,GW4,GW3,GW2,GW1,GW0};
    float ssum = 0.f;
    #pragma unroll
    for (int d = 0; d < 16; d++) {
        float b0=0.f,b1=0.f,b2=0.f,b3=0.f,b4=0.f;
        #pragma unroll
        for (int k = 0; k < 11; k++) {
            int dd = d - 5 + k;
            dd = dd < 0 ? 0 : (dd > 15 ? 15 : dd);   // compile-time after unroll
            float w = wq[k];                          // literal after unroll
            b0 = fmaf(i0[dd], w, b0);
            b1 = fmaf(i1[dd], w, b1);
            b2 = fmaf(i2[dd], w, b2);
            b3 = fmaf(i3[dd], w, b3);
            b4 = fmaf(i4[dd], w, b4);
        }
        float mu1 = b0, mu2 = b1;
        float mu1s = mu1*mu1, mu2s = mu2*mu2, mu12 = mu1*mu2;
        float s1 = b2 - mu1s, s2 = b3 - mu2s, s12 = b4 - mu12;
        float v1 = 2.f*s12 + C2F;
        float v2 = s1 + s2 + C2F;
        float num = (2.f*mu12 + C1F) * v1;
        float den = (mu1s + mu2s + C1F) * v2;
        ssum += __fdividef(num, den);
    }

    __shared__ float red[256];
    red[tid] = ssum;
    __syncthreads();
    #pragma unroll
    for (int s = 128; s > 0; s >>= 1) {
        if (tid < s) red[tid] += red[tid + s];
        __syncthreads();
    }
    if (tid == 0) atomicAdd(&g_acc[4 + n], (double)red[0]);
}

__global__ void final_kernel(float* out, int out_size) {
    if (threadIdx.x == 0 && blockIdx.x == 0) {
        double psnr = 0.0, ssim = 0.0;
        for (int n = 0; n < NB; n++) {
            double mse = g_acc[n] / (double)VOL;
            psnr += 10.0 * log10(1.0 / mse);
            ssim += g_acc[4 + n] / (double)VOL;
        }
        if (out_size > 0) out[0] = (float)psnr;
        if (out_size > 1) out[1] = (float)ssim;
        if (out_size > 2) out[2] = (float)NB;
        for (int i = 3; i < out_size; i++) out[i] = 0.f;
        // Restore the zero invariant for the next replay.
        for (int i = 0; i < 8; i++) g_acc[i] = 0.0;
    }
}

extern "C" void kernel_launch(void* const* d_in, const int* in_sizes, int n_in,
                              void* d_out, int out_size) {
    const float* pred = (const float*)d_in[0];
    const float* gt   = (const float*)d_in[1];

    dim3 g1(WW/32, HH/32, NB*DD);
    blur2d_kernel<<<g1, 256>>>(pred, gt);

    dim3 g2(PLANE/256, NB);
    ssim_d_kernel<<<g2, 256>>>();

    final_kernel<<<1, 32>>>((float*)d_out, out_size);
}

// round 5
// speedup vs baseline: 1.7740x; 1.3268x over previous
#include <cuda_runtime.h>
#include <cuda_fp16.h>
#include <math.h>

#define NB 4
#define DD 16
#define HH 512
#define WW 512
#define PLANE (HH*WW)
#define VOL (DD*PLANE)
#define TOT (NB*VOL)
#define C1F 0.0001f
#define C2F 0.0009f

// Gaussian weights as literals -> FFMA-imm (rt_SMSP=1).
#define GW0 0.00102838f
#define GW1 0.00759875f
#define GW2 0.03600077f
#define GW3 0.10936069f
#define GW4 0.21300554f
#define GW5 0.26601173f

// Blurred fields, fp16: (p,g) packed, (p^2,g^2) packed, p*g scalar. [N*D,H,W]
__device__ __half2 g01[TOT];
__device__ __half2 g23[TOT];
__device__ __half  g4v[TOT];
// [0..3] per-n sum (p-g)^2 ; [4..7] per-n sum ssim_map. Zeroed at load;
// final_kernel re-zeroes after reading so each replay starts clean.
__device__ double g_acc[8];

__device__ __forceinline__ float blur11(const float* v) {
    float a;
    a = v[0]  * GW0;
    a = fmaf(v[1],  GW1, a);
    a = fmaf(v[2],  GW2, a);
    a = fmaf(v[3],  GW3, a);
    a = fmaf(v[4],  GW4, a);
    a = fmaf(v[5],  GW5, a);
    a = fmaf(v[6],  GW4, a);
    a = fmaf(v[7],  GW3, a);
    a = fmaf(v[8],  GW2, a);
    a = fmaf(v[9],  GW1, a);
    a = fmaf(v[10], GW0, a);
    return a;
}

// Fused field-gen + W-blur + H-blur per (n,d) slice tile; PSNR fused.
// SoA scalar smem, strides chosen conflict-free (45 for tiles, 33 for tmp).
__global__ __launch_bounds__(256) void blur2d_kernel(
    const float* __restrict__ pred, const float* __restrict__ gt)
{
    __shared__ float sp[42][45];   // p   (stride 45: odd -> conflict-free W reads)
    __shared__ float sg[42][45];   // g
    __shared__ float tx[42][33];   // tmp (stride 33 -> conflict-free STS/LDS)
    __shared__ float ty[42][33];
    __shared__ float red[256];

    int z = blockIdx.z;
    int n = z >> 4;
    const float* pz = pred + (size_t)z * PLANE;
    const float* gz = gt   + (size_t)z * PLANE;
    int h0 = blockIdx.y * 32 - 5;
    int w0 = blockIdx.x * 32 - 5;
    int hb = blockIdx.y * 32, wb = blockIdx.x * 32;
    int tid = threadIdx.x;

    // ---- Load 42x42 tile (clamped = replicate pad) ----
    for (int i = tid; i < 42*42; i += 256) {
        int r = i / 42, c = i - r*42;
        int hh = min(max(h0 + r, 0), HH-1);
        int ww = min(max(w0 + c, 0), WW-1);
        sp[r][c] = pz[hh*WW + ww];
        sg[r][c] = gz[hh*WW + ww];
    }
    __syncthreads();

    // ---- PSNR partial over interior 32x32 ----
    float psum = 0.f;
    #pragma unroll
    for (int i = 0; i < 4; i++) {
        int j = tid + i*256;
        int r = 5 + (j >> 5), c = 5 + (j & 31);
        float d = sp[r][c] - sg[r][c];
        psum = fmaf(d, d, psum);
    }

    int rW = tid >> 2, chW = (tid & 3) * 8;   // W-pass coords (tid < 168)
    int hch = tid >> 5, cH = tid & 31;        // H-pass coords (tid < 128)

    // ======== Pass A: {p, g} ========
    if (tid < 168) {
        float vx[18], vy[18];
        #pragma unroll
        for (int k = 0; k < 18; k++) { vx[k] = sp[rW][chW + k]; vy[k] = sg[rW][chW + k]; }
        #pragma unroll
        for (int o = 0; o < 8; o++) {
            tx[rW][chW + o] = blur11(vx + o);
            ty[rW][chW + o] = blur11(vy + o);
        }
    }
    __syncthreads();
    if (tid < 128) {
        float vx[18], vy[18];
        #pragma unroll
        for (int k = 0; k < 18; k++) { vx[k] = tx[hch*8 + k][cH]; vy[k] = ty[hch*8 + k][cH]; }
        __half2* o01 = &g01[(size_t)z * PLANE];
        #pragma unroll
        for (int o = 0; o < 8; o++) {
            int row = hb + hch*8 + o;
            o01[row*WW + wb + cH] = __floats2half2_rn(blur11(vx + o), blur11(vy + o));
        }
    }
    __syncthreads();

    // ======== Pass B: {p^2, g^2} (squared on load; no extra tiles) ========
    if (tid < 168) {
        float vx[18], vy[18];
        #pragma unroll
        for (int k = 0; k < 18; k++) {
            float a = sp[rW][chW + k], b = sg[rW][chW + k];
            vx[k] = a * a; vy[k] = b * b;
        }
        #pragma unroll
        for (int o = 0; o < 8; o++) {
            tx[rW][chW + o] = blur11(vx + o);
            ty[rW][chW + o] = blur11(vy + o);
        }
    }
    __syncthreads();
    if (tid < 128) {
        float vx[18], vy[18];
        #pragma unroll
        for (int k = 0; k < 18; k++) { vx[k] = tx[hch*8 + k][cH]; vy[k] = ty[hch*8 + k][cH]; }
        __half2* o23 = &g23[(size_t)z * PLANE];
        #pragma unroll
        for (int o = 0; o < 8; o++) {
            int row = hb + hch*8 + o;
            o23[row*WW + wb + cH] = __floats2half2_rn(blur11(vx + o), blur11(vy + o));
        }
    }
    __syncthreads();

    // ======== Pass C: p*g ========
    if (tid < 168) {
        float v[18];
        #pragma unroll
        for (int k = 0; k < 18; k++) v[k] = sp[rW][chW + k] * sg[rW][chW + k];
        #pragma unroll
        for (int o = 0; o < 8; o++) tx[rW][chW + o] = blur11(v + o);
    }
    __syncthreads();
    if (tid < 128) {
        float v[18];
        #pragma unroll
        for (int k = 0; k < 18; k++) v[k] = tx[hch*8 + k][cH];
        __half* o4 = &g4v[(size_t)z * PLANE];
        #pragma unroll
        for (int o = 0; o < 8; o++) {
            int row = hb + hch*8 + o;
            o4[row*WW + wb + cH] = __float2half_rn(blur11(v + o));
        }
    }
    __syncthreads();

    // ---- PSNR block reduce ----
    red[tid] = psum;
    __syncthreads();
    #pragma unroll
    for (int s = 128; s > 0; s >>= 1) {
        if (tid < s) red[tid] += red[tid + s];
        __syncthreads();
    }
    if (tid == 0) atomicAdd(&g_acc[n], (double)red[0]);
}

// D-blur in registers (D=16, clamped) + SSIM pointwise + reduction.
__global__ __launch_bounds__(256) void ssim_d_kernel() {
    int tid = threadIdx.x;
    int idx = blockIdx.x * 256 + tid;
    int n   = blockIdx.y;
    size_t base = (size_t)n * VOL + idx;

    float i0[16], i1[16], i2[16], i3[16], i4[16];
    #pragma unroll
    for (int d = 0; d < 16; d++) {
        size_t off = base + (size_t)d * PLANE;
        float2 a = __half22float2(g01[off]);
        float2 b = __half22float2(g23[off]);
        i0[d] = a.x; i1[d] = a.y;
        i2[d] = b.x; i3[d] = b.y;
        i4[d] = __half2float(g4v[off]);
    }

    const float wq[11] = {GW0,GW1,GW2,GW3,GW4,GW5,GW4,GW3,GW2,GW1,GW0};
    float ssum = 0.f;
    #pragma unroll
    for (int d = 0; d < 16; d++) {
        float b0=0.f,b1=0.f,b2=0.f,b3=0.f,b4=0.f;
        #pragma unroll
        for (int k = 0; k < 11; k++) {
            int dd = d - 5 + k;
            dd = dd < 0 ? 0 : (dd > 15 ? 15 : dd);   // compile-time after unroll
            float w = wq[k];                          // literal after unroll
            b0 = fmaf(i0[dd], w, b0);
            b1 = fmaf(i1[dd], w, b1);
            b2 = fmaf(i2[dd], w, b2);
            b3 = fmaf(i3[dd], w, b3);
            b4 = fmaf(i4[dd], w, b4);
        }
        float mu1 = b0, mu2 = b1;
        float mu1s = mu1*mu1, mu2s = mu2*mu2, mu12 = mu1*mu2;
        float s1 = b2 - mu1s, s2 = b3 - mu2s, s12 = b4 - mu12;
        float v1 = 2.f*s12 + C2F;
        float v2 = s1 + s2 + C2F;
        float num = (2.f*mu12 + C1F) * v1;
        float den = (mu1s + mu2s + C1F) * v2;
        ssum += __fdividef(num, den);
    }

    __shared__ float red[256];
    red[tid] = ssum;
    __syncthreads();
    #pragma unroll
    for (int s = 128; s > 0; s >>= 1) {
        if (tid < s) red[tid] += red[tid + s];
        __syncthreads();
    }
    if (tid == 0) atomicAdd(&g_acc[4 + n], (double)red[0]);
}

__global__ void final_kernel(float* out, int out_size) {
    if (threadIdx.x == 0 && blockIdx.x == 0) {
        double psnr = 0.0, ssim = 0.0;
        for (int n = 0; n < NB; n++) {
            double mse = g_acc[n] / (double)VOL;
            psnr += 10.0 * log10(1.0 / mse);
            ssim += g_acc[4 + n] / (double)VOL;
        }
        if (out_size > 0) out[0] = (float)psnr;
        if (out_size > 1) out[1] = (float)ssim;
        if (out_size > 2) out[2] = (float)NB;
        for (int i = 3; i < out_size; i++) out[i] = 0.f;
        for (int i = 0; i < 8; i++) g_acc[i] = 0.0;  // restore invariant
    }
}

extern "C" void kernel_launch(void* const* d_in, const int* in_sizes, int n_in,
                              void* d_out, int out_size) {
    const float* pred = (const float*)d_in[0];
    const float* gt   = (const float*)d_in[1];

    dim3 g1(WW/32, HH/32, NB*DD);
    blur2d_kernel<<<g1, 256>>>(pred, gt);

    dim3 g2(PLANE/256, NB);
    ssim_d_kernel<<<g2, 256>>>();

    final_kernel<<<1, 32>>>((float*)d_out, out_size);
}